// round 13
// baseline (speedup 1.0000x reference)
#include <cuda_runtime.h>
#include <cuda_bf16.h>
#include <math.h>
#include <cstdint>

// Shapes: B=16,T=512,D=80 -> N=8192 rows, K=80
#define NROWS   8192
#define DDIM    80
#define BI      128
#define BJ      128
#define STRIDE  88                  // smem row stride in bf16 (176B = 11x16B)
#define TILEB   (BI * STRIDE * 2)   // 22528 B per tile buffer
#define NCTA    296                 // persistent: one full wave at occ 2 on 148 SMs

// ---------------- scratch (__device__ globals; no allocs allowed) -----------
__device__ __align__(16) __nv_bfloat16 g_abf[NROWS * DDIM];
__device__ __align__(16) __nv_bfloat16 g_tbf[NROWS * DDIM];
__device__ float g_pos[NROWS];
__device__ float g_rowsum[NROWS];
__device__ int   g_cnt = 0;         // monotonic ticket counter (replay-safe)

// ---------------- helpers ---------------------------------------------------
__device__ __forceinline__ uint32_t smem_u32(const void* p) {
    uint32_t a;
    asm("{ .reg .u64 t; cvta.to.shared.u64 t, %1; cvt.u32.u64 %0, t; }" : "=r"(a) : "l"(p));
    return a;
}
__device__ __forceinline__ void cp_async16(uint32_t dst, const void* src) {
    asm volatile("cp.async.cg.shared.global [%0], [%1], 16;" :: "r"(dst), "l"(src) : "memory");
}
#define CP_COMMIT() asm volatile("cp.async.commit_group;" ::: "memory")
#define CP_WAIT0()  asm volatile("cp.async.wait_group 0;" ::: "memory")
#define CP_WAIT1()  asm volatile("cp.async.wait_group 1;" ::: "memory")

__device__ __forceinline__ void ldsm_x4(uint32_t& r0, uint32_t& r1, uint32_t& r2, uint32_t& r3, uint32_t addr) {
    asm volatile("ldmatrix.sync.aligned.m8n8.x4.shared.b16 {%0,%1,%2,%3}, [%4];"
                 : "=r"(r0), "=r"(r1), "=r"(r2), "=r"(r3) : "r"(addr));
}
__device__ __forceinline__ void mma16816(float& c0, float& c1, float& c2, float& c3,
                                         uint32_t a0, uint32_t a1, uint32_t a2, uint32_t a3,
                                         uint32_t b0, uint32_t b1) {
    asm volatile("mma.sync.aligned.m16n8k16.row.col.f32.bf16.bf16.f32 "
                 "{%0,%1,%2,%3}, {%4,%5,%6,%7}, {%8,%9}, {%0,%1,%2,%3};"
                 : "+f"(c0), "+f"(c1), "+f"(c2), "+f"(c3)
                 : "r"(a0), "r"(a1), "r"(a2), "r"(a3), "r"(b0), "r"(b1));
}

// replay-safe grid barrier: monotonic ticket arrival (1 atomic), VOLATILE-LOAD
// spin with nanosleep backoff (no atomic-ALU serialization while polling)
__device__ __forceinline__ void grid_bar() {
    __syncthreads();
    if (threadIdx.x == 0) {
        __threadfence();
        int t = atomicAdd(&g_cnt, 1);
        int target = (t / NCTA + 1) * NCTA;
        volatile int* c = &g_cnt;
        while (*c < target) { __nanosleep(64); }
        __threadfence();
    }
    __syncthreads();
}

// copy one 128x80 bf16 tile (row-major, 160B/row) into padded smem tile
__device__ __forceinline__ void load_tile(uint32_t smem_dst, const char* gsrc, int tid) {
    #pragma unroll
    for (int w = 0; w < 5; w++) {
        int c = tid + w * 256;
        int r = c / 10, q = c % 10;
        cp_async16(smem_dst + (r * STRIDE + q * 8) * 2, gsrc + r * 160 + q * 16);
    }
}

// flush: rs holds sum of (P2(x)-1); add back ntiles*8 ones per lane
__device__ __forceinline__ void flush_rs(float rs[8], int ntiles, int itile, int wm, int lane) {
    int g = lane >> 2;
    float ones = 8.0f * (float)ntiles;
    #pragma unroll
    for (int q = 0; q < 8; q++) {
        float v = rs[q] + ones;
        v += __shfl_xor_sync(0xffffffffu, v, 1);
        v += __shfl_xor_sync(0xffffffffu, v, 2);
        if ((lane & 3) == 0) {
            int mf = q >> 1;
            int row = itile * BI + wm * 64 + mf * 16 + g + (q & 1) * 8;
            atomicAdd(&g_rowsum[row], v);
        }
        rs[q] = 0.0f;
    }
}

// =============== Fused persistent kernel ====================================
__global__ void __launch_bounds__(256, 2) fused_kernel(
        const float* __restrict__ o, const float* __restrict__ t,
        float* __restrict__ out) {
    extern __shared__ __nv_bfloat16 sm[];
    uint32_t as_base = smem_u32(sm);                       // A: 2 stages
    uint32_t bs_base = as_base + 2 * TILEB;                // B: 3 stages

    int tid = threadIdx.x, wid = tid >> 5, lane = tid & 31;
    int b = blockIdx.x;

    // ---------------- Phase A: normalize + pos + zero rowsum ----------------
    {
        if (b == 0 && tid == 0) out[0] = 0.0f;             // reset for replay
        int wg = b * 8 + wid;                              // 2368 global warps
        for (int row = wg; row < NROWS; row += NCTA * 8) {
            const float4* op = (const float4*)(o + (size_t)row * DDIM);
            const float4* tp = (const float4*)(t + (size_t)row * DDIM);
            float4 ov = make_float4(0.f, 0.f, 0.f, 0.f), tv = ov;
            if (lane < 20) { ov = op[lane]; tv = tp[lane]; }

            float so = ov.x*ov.x + ov.y*ov.y + ov.z*ov.z + ov.w*ov.w;
            float st = tv.x*tv.x + tv.y*tv.y + tv.z*tv.z + tv.w*tv.w;
            float sd = ov.x*tv.x + ov.y*tv.y + ov.z*tv.z + ov.w*tv.w;
            #pragma unroll
            for (int m = 16; m > 0; m >>= 1) {
                so += __shfl_xor_sync(0xffffffffu, so, m);
                st += __shfl_xor_sync(0xffffffffu, st, m);
                sd += __shfl_xor_sync(0xffffffffu, sd, m);
            }
            float rno = rsqrtf(so);                        // norms ~9; eps unreachable
            float rnt = rsqrtf(st);

            if (lane < 20) {
                __nv_bfloat162 a0 = {__float2bfloat16(ov.x*rno), __float2bfloat16(ov.y*rno)};
                __nv_bfloat162 a1 = {__float2bfloat16(ov.z*rno), __float2bfloat16(ov.w*rno)};
                __nv_bfloat162 b0 = {__float2bfloat16(tv.x*rnt), __float2bfloat16(tv.y*rnt)};
                __nv_bfloat162 b1 = {__float2bfloat16(tv.z*rnt), __float2bfloat16(tv.w*rnt)};
                ((__nv_bfloat162*)(g_abf + (size_t)row * DDIM))[lane*2]   = a0;
                ((__nv_bfloat162*)(g_abf + (size_t)row * DDIM))[lane*2+1] = a1;
                ((__nv_bfloat162*)(g_tbf + (size_t)row * DDIM))[lane*2]   = b0;
                ((__nv_bfloat162*)(g_tbf + (size_t)row * DDIM))[lane*2+1] = b1;
            }
            if (lane == 0) {
                g_pos[row] = sd * rno * rnt;               // exact fp32 diagonal
                g_rowsum[row] = 0.0f;
            }
        }
    }
    grid_bar();

    // ---------------- Phase B: persistent GEMM (proven R10 loop) ------------
    {
        int wm = wid & 1, wn = wid >> 1;                   // warp tile 64M x 32N
        int start, cnt;
        if (b < 248) { start = b * 14; cnt = 14; }
        else         { start = 3472 + (b - 248) * 13; cnt = 13; }
        int i_first = start >> 6;

        {
            int j0 = start & 63;
            load_tile(as_base, (const char*)(g_abf + (size_t)i_first * BI * DDIM), tid);
            load_tile(bs_base, (const char*)(g_tbf + (size_t)j0 * BJ * DDIM), tid);
            CP_COMMIT();
            if (cnt > 1) {
                int p1 = start + 1;
                int i1 = p1 >> 6, j1 = p1 & 63;
                if (i1 != i_first)
                    load_tile(as_base + TILEB, (const char*)(g_abf + (size_t)i1 * BI * DDIM), tid);
                load_tile(bs_base + TILEB, (const char*)(g_tbf + (size_t)j1 * BJ * DDIM), tid);
                CP_COMMIT();
            }
        }

        float rs[8];
        #pragma unroll
        for (int q = 0; q < 8; q++) rs[q] = 0.0f;
        int ntiles = 0;

        int aRow = wm * 64 + (lane & 7) + 8 * ((lane >> 3) & 1);
        int aCol16 = (lane >> 4);
        int bRow = wn * 32 + (lane & 7) + 8 * (lane >> 4);
        int bCol16 = ((lane >> 3) & 1);

        for (int k = 0; k < cnt; k++) {
            int p = start + k;
            int i = p >> 6;

            if (k + 1 < cnt) { CP_WAIT1(); } else { CP_WAIT0(); }
            __syncthreads();

            if (k + 2 < cnt) {
                int p2 = p + 2;
                int i2 = p2 >> 6, j2 = p2 & 63;
                if (i2 != ((p + 1) >> 6))
                    load_tile(as_base + TILEB, (const char*)(g_abf + (size_t)i2 * BI * DDIM), tid);
                load_tile(bs_base + ((k + 2) % 3) * TILEB,
                          (const char*)(g_tbf + (size_t)j2 * BJ * DDIM), tid);
                CP_COMMIT();
            }

            float acc[4][4][4];
            #pragma unroll
            for (int mf = 0; mf < 4; mf++)
                #pragma unroll
                for (int nf = 0; nf < 4; nf++)
                    #pragma unroll
                    for (int c = 0; c < 4; c++) acc[mf][nf][c] = 0.0f;

            uint32_t abuf = as_base + ((i != i_first) ? TILEB : 0);
            uint32_t bbuf = bs_base + (k % 3) * TILEB;
            #pragma unroll
            for (int ks = 0; ks < 5; ks++) {
                int k0 = ks * 16;
                uint32_t a[4][4], bb[2][4];
                #pragma unroll
                for (int mf = 0; mf < 4; mf++)
                    ldsm_x4(a[mf][0], a[mf][1], a[mf][2], a[mf][3],
                            abuf + ((aRow + mf * 16) * STRIDE + k0 + aCol16 * 8) * 2);
                #pragma unroll
                for (int h = 0; h < 2; h++)
                    ldsm_x4(bb[h][0], bb[h][1], bb[h][2], bb[h][3],
                            bbuf + ((bRow + h * 16) * STRIDE + k0 + bCol16 * 8) * 2);
                #pragma unroll
                for (int mf = 0; mf < 4; mf++)
                    #pragma unroll
                    for (int nf = 0; nf < 4; nf++)
                        mma16816(acc[mf][nf][0], acc[mf][nf][1], acc[mf][nf][2], acc[mf][nf][3],
                                 a[mf][0], a[mf][1], a[mf][2], a[mf][3],
                                 bb[nf >> 1][(nf & 1) * 2 + 0], bb[nf >> 1][(nf & 1) * 2 + 1]);
            }

            // epilogue: deg-2 exp, constant folded (2 FFMA/elem); diagonal fixed in C
            #pragma unroll
            for (int mf = 0; mf < 4; mf++)
                #pragma unroll
                for (int nf = 0; nf < 4; nf++)
                    #pragma unroll
                    for (int c = 0; c < 4; c++) {
                        float x = acc[mf][nf][c];
                        float t2 = fmaf(x, 0.5f, 1.0f);
                        rs[mf * 2 + (c >> 1)] = fmaf(t2, x, rs[mf * 2 + (c >> 1)]);
                    }
            ntiles++;

            if (k + 1 >= cnt || ((p + 1) >> 6) != i) {
                flush_rs(rs, ntiles, i, wm, lane);
                ntiles = 0;
            }
        }
    }
    grid_bar();

    // ---------------- Phase C: reduce with exact diagonal correction --------
    if (b < 32) {
        __shared__ float sbuf[8];
        int base = b * 256;
        float p = g_pos[base + tid];
        float p2 = fmaf(fmaf(p, 0.5f, 1.0f), p, 1.0f);
        float rsum = g_rowsum[base + tid] + (__expf(p) - p2);
        float s = __logf(rsum) - p;
        #pragma unroll
        for (int m = 16; m > 0; m >>= 1) s += __shfl_xor_sync(0xffffffffu, s, m);
        if (lane == 0) sbuf[wid] = s;
        __syncthreads();
        if (tid < 32) {
            float v = (tid < 8) ? sbuf[tid] : 0.0f;
            #pragma unroll
            for (int m = 4; m > 0; m >>= 1) v += __shfl_xor_sync(0xffffffffu, v, m);
            if (tid == 0) atomicAdd(out, v * (1.0f / (float)NROWS));
        }
    }
}

extern "C" void kernel_launch(void* const* d_in, const int* in_sizes, int n_in,
                              void* d_out, int out_size) {
    const float* mel_outputs = (const float*)d_in[0];
    const float* mel_targets = (const float*)d_in[1];
    float* out = (float*)d_out;

    const int smem_bytes = 5 * TILEB;                      // 112640 B (A x2 + B x3)
    cudaFuncSetAttribute(fused_kernel,
                         cudaFuncAttributeMaxDynamicSharedMemorySize, smem_bytes);
    fused_kernel<<<NCTA, 256, smem_bytes>>>(mel_outputs, mel_targets, out);
}

// round 15
// speedup vs baseline: 1.1890x; 1.1890x over previous
#include <cuda_runtime.h>
#include <math.h>
#include <cstdint>

// Shapes: B=16,T=512,D=80 -> N=8192 rows, K=80
// Algebraic form: rowsum_i = N + o_i.s + 0.5*o_i^T M o_i + (exp(p)-P2(p)),
//   s = sum_j t_j,  M = sum_j t_j t_j^T  (t,o L2-normalized, all fp32)
#define NROWS 8192
#define DDIM  80
#define PAD   81                 // smem row pad (81 coprime 32 -> conflict-free)
#define MSZ   (PAD * PAD)        // 6561
#define K1CTA 128
#define ROWS1 (NROWS / K1CTA)    // 64 t-rows per stats CTA
#define K3CTA 256
#define ROWS3 (NROWS / K3CTA)    // 32 rows per rowloss CTA

// ---------------- scratch (__device__ globals; no allocs allowed) -----------
__device__ float g_Mp[K1CTA * MSZ];    // per-CTA M partials (3.36 MB)
__device__ float g_sp[K1CTA * PAD];    // per-CTA s partials
__device__ float g_M[MSZ];
__device__ float g_s[PAD];

// =============== K1: per-CTA M and s partials over 64 t-rows ================
__global__ void __launch_bounds__(256) stats_kernel(const float* __restrict__ t) {
    __shared__ float T[ROWS1][PAD];
    __shared__ float rn[ROWS1];
    int tid = threadIdx.x, b = blockIdx.x;
    size_t base = (size_t)b * ROWS1 * DDIM;

    for (int i = tid; i < ROWS1 * DDIM; i += 256)
        T[i / DDIM][i % DDIM] = t[base + i];
    __syncthreads();

    if (tid < ROWS1) {                       // row L2 norms
        float s = 0.f;
        #pragma unroll 8
        for (int e = 0; e < DDIM; e++) s = fmaf(T[tid][e], T[tid][e], s);
        rn[tid] = rsqrtf(s);                 // eps branch unreachable (norms ~9)
    }
    __syncthreads();
    for (int i = tid; i < ROWS1 * DDIM; i += 256)
        T[i / DDIM][i % DDIM] *= rn[i / DDIM];
    __syncthreads();

    if (tid < DDIM) {                        // s partial (column sums)
        float s = 0.f;
        #pragma unroll 8
        for (int r = 0; r < ROWS1; r++) s += T[r][tid];
        g_sp[b * PAD + tid] = s;
    }

    // M partial: each thread owns a 5x5 (d1,d2) block
    int d1 = (tid >> 4) * 5, d2 = (tid & 15) * 5;
    float acc[5][5] = {};
    #pragma unroll 4
    for (int r = 0; r < ROWS1; r++) {
        float a[5], c[5];
        #pragma unroll
        for (int k = 0; k < 5; k++) { a[k] = T[r][d1 + k]; c[k] = T[r][d2 + k]; }
        #pragma unroll
        for (int k = 0; k < 5; k++)
            #pragma unroll
            for (int j = 0; j < 5; j++) acc[k][j] = fmaf(a[k], c[j], acc[k][j]);
    }
    float* mp = g_Mp + (size_t)b * MSZ;
    #pragma unroll
    for (int k = 0; k < 5; k++)
        #pragma unroll
        for (int j = 0; j < 5; j++) mp[(d1 + k) * PAD + (d2 + j)] = acc[k][j];
}

// =============== K2: sum partials -> g_M, g_s; zero out =====================
__global__ void __launch_bounds__(256) reduce_stats_kernel(float* __restrict__ out) {
    int g = blockIdx.x * 256 + threadIdx.x;
    if (g == 0) out[0] = 0.f;                // reset for every graph replay
    if (g < MSZ) {
        int e = g / PAD, d = g % PAD;
        float s0 = 0.f, s1 = 0.f, s2 = 0.f, s3 = 0.f;
        if (e < DDIM && d < DDIM) {
            #pragma unroll 4
            for (int c = 0; c < K1CTA; c += 4) {
                s0 += g_Mp[(size_t)(c + 0) * MSZ + g];
                s1 += g_Mp[(size_t)(c + 1) * MSZ + g];
                s2 += g_Mp[(size_t)(c + 2) * MSZ + g];
                s3 += g_Mp[(size_t)(c + 3) * MSZ + g];
            }
        }
        g_M[g] = (s0 + s1) + (s2 + s3);
    } else if (g < MSZ + PAD) {
        int e = g - MSZ;
        float s = 0.f;
        if (e < DDIM)
            #pragma unroll 4
            for (int c = 0; c < K1CTA; c++) s += g_sp[c * PAD + e];
        g_s[e] = s;
    }
}

// =============== K3: per-row quadratic form + loss ==========================
__global__ void __launch_bounds__(256, 2) rowloss_kernel(
        const float* __restrict__ o, const float* __restrict__ t,
        float* __restrict__ out) {
    __shared__ float Msm[MSZ];               // 26244 B
    __shared__ float Osm[ROWS3][PAD];        // 10368 B
    __shared__ float Tsm[ROWS3][PAD];        // 10368 B
    __shared__ float ssm[PAD];
    __shared__ float rno[ROWS3], pos[ROWS3], qsm[ROWS3];
    __shared__ float wsum[8];

    int tid = threadIdx.x, b = blockIdx.x, lane = tid & 31;
    size_t base = (size_t)b * ROWS3 * DDIM;

    for (int i = tid; i < ROWS3 * DDIM; i += 256) {
        int r = i / DDIM, e = i % DDIM;
        Osm[r][e] = o[base + i];
        Tsm[r][e] = t[base + i];
    }
    for (int i = tid; i < MSZ; i += 256) Msm[i] = g_M[i];
    if (tid < PAD) ssm[tid] = g_s[tid];
    __syncthreads();

    if (tid < ROWS3) {                       // norms + exact fp32 pos
        float so = 0.f, st = 0.f, sd = 0.f;
        #pragma unroll 8
        for (int e = 0; e < DDIM; e++) {
            float a = Osm[tid][e], c = Tsm[tid][e];
            so = fmaf(a, a, so); st = fmaf(c, c, st); sd = fmaf(a, c, sd);
        }
        float rn = rsqrtf(so);
        rno[tid] = rn;
        pos[tid] = sd * rn * rsqrtf(st);
    }
    __syncthreads();
    for (int i = tid; i < ROWS3 * DDIM; i += 256)
        Osm[i / DDIM][i % DDIM] *= rno[i / DDIM];
    __syncthreads();

    // quadratic form q_r = o_r^T M o_r : thread (ty,tx) = 2 rows x 5 dims
    int ty = tid >> 4, tx = tid & 15;
    int r0 = ty * 2, d0 = tx * 5;
    float ob[2][5];
    #pragma unroll
    for (int ri = 0; ri < 2; ri++)
        #pragma unroll
        for (int k = 0; k < 5; k++) ob[ri][k] = Osm[r0 + ri][d0 + k];
    float q0 = 0.f, q1 = 0.f;
    #pragma unroll 8
    for (int e = 0; e < DDIM; e++) {
        const float* mrow = Msm + e * PAD + d0;
        float m0 = mrow[0], m1 = mrow[1], m2 = mrow[2], m3 = mrow[3], m4 = mrow[4];
        float w0 = m0 * ob[0][0];
        w0 = fmaf(m1, ob[0][1], w0); w0 = fmaf(m2, ob[0][2], w0);
        w0 = fmaf(m3, ob[0][3], w0); w0 = fmaf(m4, ob[0][4], w0);
        q0 = fmaf(w0, Osm[r0][e], q0);
        float w1 = m0 * ob[1][0];
        w1 = fmaf(m1, ob[1][1], w1); w1 = fmaf(m2, ob[1][2], w1);
        w1 = fmaf(m3, ob[1][3], w1); w1 = fmaf(m4, ob[1][4], w1);
        q1 = fmaf(w1, Osm[r0 + 1][e], q1);
    }
    #pragma unroll
    for (int m = 8; m > 0; m >>= 1) {        // reduce over 16 tx lanes
        q0 += __shfl_xor_sync(0xffffffffu, q0, m);
        q1 += __shfl_xor_sync(0xffffffffu, q1, m);
    }
    if (tx == 0) { qsm[r0] = q0; qsm[r0 + 1] = q1; }
    __syncthreads();

    // finalize rows + CTA reduction
    float loss = 0.f;
    if (tid < ROWS3) {
        float lin = 0.f;
        #pragma unroll 8
        for (int e = 0; e < DDIM; e++) lin = fmaf(ssm[e], Osm[tid][e], lin);
        float p = pos[tid];
        float corr = __expf(p) - fmaf(fmaf(p, 0.5f, 1.0f), p, 1.0f);
        float rowsum = (float)NROWS + lin + 0.5f * qsm[tid] + corr;
        loss = __logf(rowsum) - p;
    }
    #pragma unroll
    for (int m = 16; m > 0; m >>= 1) loss += __shfl_xor_sync(0xffffffffu, loss, m);
    if (lane == 0) wsum[tid >> 5] = loss;
    __syncthreads();
    if (tid == 0) {
        float v = wsum[0] + wsum[1];         // warp 0 carries rows; wsum[1]=0
        atomicAdd(out, v * (1.0f / (float)NROWS));
    }
}

extern "C" void kernel_launch(void* const* d_in, const int* in_sizes, int n_in,
                              void* d_out, int out_size) {
    const float* mel_outputs = (const float*)d_in[0];
    const float* mel_targets = (const float*)d_in[1];
    float* out = (float*)d_out;

    stats_kernel<<<K1CTA, 256>>>(mel_targets);
    reduce_stats_kernel<<<(MSZ + PAD + 255) / 256, 256>>>(out);
    rowloss_kernel<<<K3CTA, 256>>>(mel_outputs, mel_targets, out);
}

// round 16
// speedup vs baseline: 1.1938x; 1.0041x over previous
#include <cuda_runtime.h>
#include <math.h>
#include <cstdint>

// Shapes: B=16,T=512,D=80 -> N=8192 rows, K=80
// Algebraic form: rowsum_i = N + o_i.s + 0.5*o_i^T M o_i + (exp(p)-P2(p)),
//   s = sum_j t_j,  M = sum_j t_j t_j^T  (t,o L2-normalized, all fp32)
#define NROWS 8192
#define DDIM  80
#define PAD   81                 // smem row pad (81 coprime 32 -> conflict-free)
#define MSZ   (PAD * PAD)        // 6561
#define K1CTA 128
#define ROWS1 (NROWS / K1CTA)    // 64 t-rows per stats CTA
#define K3CTA 256
#define ROWS3 (NROWS / K3CTA)    // 32 rows per rowloss CTA

// ---------------- scratch (__device__ globals; no allocs allowed) -----------
__device__ float g_Mp[K1CTA * MSZ];    // per-CTA M partials (3.36 MB)
__device__ float g_sp[K1CTA * PAD];    // per-CTA s partials
__device__ float g_M[MSZ];
__device__ float g_s[PAD];

// =============== K1: per-CTA M and s partials over 64 t-rows ================
__global__ void __launch_bounds__(256) stats_kernel(const float* __restrict__ t) {
    __shared__ float T[ROWS1][PAD];
    __shared__ float rn[ROWS1];
    int tid = threadIdx.x, b = blockIdx.x;
    size_t base = (size_t)b * ROWS1 * DDIM;

    for (int i = tid; i < ROWS1 * DDIM; i += 256)
        T[i / DDIM][i % DDIM] = t[base + i];
    __syncthreads();

    if (tid < ROWS1) {                       // row L2 norms
        float s = 0.f;
        #pragma unroll 8
        for (int e = 0; e < DDIM; e++) s = fmaf(T[tid][e], T[tid][e], s);
        rn[tid] = rsqrtf(s);                 // eps branch unreachable (norms ~9)
    }
    __syncthreads();
    for (int i = tid; i < ROWS1 * DDIM; i += 256)
        T[i / DDIM][i % DDIM] *= rn[i / DDIM];
    __syncthreads();

    if (tid < DDIM) {                        // s partial (column sums)
        float s = 0.f;
        #pragma unroll 8
        for (int r = 0; r < ROWS1; r++) s += T[r][tid];
        g_sp[b * PAD + tid] = s;
    }

    // M partial: each thread owns a 5x5 (d1,d2) block
    int d1 = (tid >> 4) * 5, d2 = (tid & 15) * 5;
    float acc[5][5] = {};
    #pragma unroll 4
    for (int r = 0; r < ROWS1; r++) {
        float a[5], c[5];
        #pragma unroll
        for (int k = 0; k < 5; k++) { a[k] = T[r][d1 + k]; c[k] = T[r][d2 + k]; }
        #pragma unroll
        for (int k = 0; k < 5; k++)
            #pragma unroll
            for (int j = 0; j < 5; j++) acc[k][j] = fmaf(a[k], c[j], acc[k][j]);
    }
    float* mp = g_Mp + (size_t)b * MSZ;
    #pragma unroll
    for (int k = 0; k < 5; k++)
        #pragma unroll
        for (int j = 0; j < 5; j++) mp[(d1 + k) * PAD + (d2 + j)] = acc[k][j];
}

// =============== K2: sum partials -> g_M, g_s; zero out =====================
__global__ void __launch_bounds__(256) reduce_stats_kernel(float* __restrict__ out) {
    int g = blockIdx.x * 256 + threadIdx.x;
    if (g == 0) out[0] = 0.f;                // reset for every graph replay
    if (g < MSZ) {
        int e = g / PAD, d = g % PAD;
        float s0 = 0.f, s1 = 0.f, s2 = 0.f, s3 = 0.f;
        if (e < DDIM && d < DDIM) {
            #pragma unroll 4
            for (int c = 0; c < K1CTA; c += 4) {
                s0 += g_Mp[(size_t)(c + 0) * MSZ + g];
                s1 += g_Mp[(size_t)(c + 1) * MSZ + g];
                s2 += g_Mp[(size_t)(c + 2) * MSZ + g];
                s3 += g_Mp[(size_t)(c + 3) * MSZ + g];
            }
        }
        g_M[g] = (s0 + s1) + (s2 + s3);
    } else if (g < MSZ + PAD) {
        int e = g - MSZ;
        float s = 0.f;
        if (e < DDIM)
            #pragma unroll 4
            for (int c = 0; c < K1CTA; c++) s += g_sp[c * PAD + e];
        g_s[e] = s;
    }
}

// =============== K3: per-row quadratic form + loss ==========================
__global__ void __launch_bounds__(256, 2) rowloss_kernel(
        const float* __restrict__ o, const float* __restrict__ t,
        float* __restrict__ out) {
    __shared__ float Msm[MSZ];               // 26244 B
    __shared__ float Osm[ROWS3][PAD];        // 10368 B
    __shared__ float Tsm[ROWS3][PAD];        // 10368 B
    __shared__ float ssm[PAD];
    __shared__ float rno[ROWS3], pos[ROWS3], qsm[ROWS3];
    __shared__ float wsum[8];

    int tid = threadIdx.x, b = blockIdx.x, lane = tid & 31;
    size_t base = (size_t)b * ROWS3 * DDIM;

    for (int i = tid; i < ROWS3 * DDIM; i += 256) {
        int r = i / DDIM, e = i % DDIM;
        Osm[r][e] = o[base + i];
        Tsm[r][e] = t[base + i];
    }
    for (int i = tid; i < MSZ; i += 256) Msm[i] = g_M[i];
    if (tid < PAD) ssm[tid] = g_s[tid];
    __syncthreads();

    if (tid < ROWS3) {                       // norms + exact fp32 pos
        float so = 0.f, st = 0.f, sd = 0.f;
        #pragma unroll 8
        for (int e = 0; e < DDIM; e++) {
            float a = Osm[tid][e], c = Tsm[tid][e];
            so = fmaf(a, a, so); st = fmaf(c, c, st); sd = fmaf(a, c, sd);
        }
        float rn = rsqrtf(so);
        rno[tid] = rn;
        pos[tid] = sd * rn * rsqrtf(st);
    }
    __syncthreads();
    for (int i = tid; i < ROWS3 * DDIM; i += 256)
        Osm[i / DDIM][i % DDIM] *= rno[i / DDIM];
    __syncthreads();

    // quadratic form q_r = o_r^T M o_r : thread (ty,tx) = 2 rows x 5 dims
    int ty = tid >> 4, tx = tid & 15;
    int r0 = ty * 2, d0 = tx * 5;
    float ob[2][5];
    #pragma unroll
    for (int ri = 0; ri < 2; ri++)
        #pragma unroll
        for (int k = 0; k < 5; k++) ob[ri][k] = Osm[r0 + ri][d0 + k];
    float q0 = 0.f, q1 = 0.f;
    #pragma unroll 8
    for (int e = 0; e < DDIM; e++) {
        const float* mrow = Msm + e * PAD + d0;
        float m0 = mrow[0], m1 = mrow[1], m2 = mrow[2], m3 = mrow[3], m4 = mrow[4];
        float w0 = m0 * ob[0][0];
        w0 = fmaf(m1, ob[0][1], w0); w0 = fmaf(m2, ob[0][2], w0);
        w0 = fmaf(m3, ob[0][3], w0); w0 = fmaf(m4, ob[0][4], w0);
        q0 = fmaf(w0, Osm[r0][e], q0);
        float w1 = m0 * ob[1][0];
        w1 = fmaf(m1, ob[1][1], w1); w1 = fmaf(m2, ob[1][2], w1);
        w1 = fmaf(m3, ob[1][3], w1); w1 = fmaf(m4, ob[1][4], w1);
        q1 = fmaf(w1, Osm[r0 + 1][e], q1);
    }
    #pragma unroll
    for (int m = 8; m > 0; m >>= 1) {        // reduce over 16 tx lanes
        q0 += __shfl_xor_sync(0xffffffffu, q0, m);
        q1 += __shfl_xor_sync(0xffffffffu, q1, m);
    }
    if (tx == 0) { qsm[r0] = q0; qsm[r0 + 1] = q1; }
    __syncthreads();

    // finalize rows + CTA reduction
    float loss = 0.f;
    if (tid < ROWS3) {
        float lin = 0.f;
        #pragma unroll 8
        for (int e = 0; e < DDIM; e++) lin = fmaf(ssm[e], Osm[tid][e], lin);
        float p = pos[tid];
        float corr = __expf(p) - fmaf(fmaf(p, 0.5f, 1.0f), p, 1.0f);
        float rowsum = (float)NROWS + lin + 0.5f * qsm[tid] + corr;
        loss = __logf(rowsum) - p;
    }
    #pragma unroll
    for (int m = 16; m > 0; m >>= 1) loss += __shfl_xor_sync(0xffffffffu, loss, m);
    if (lane == 0) wsum[tid >> 5] = loss;
    __syncthreads();
    if (tid == 0) {
        float v = wsum[0] + wsum[1];         // warp 0 carries rows; wsum[1]=0
        atomicAdd(out, v * (1.0f / (float)NROWS));
    }
}

extern "C" void kernel_launch(void* const* d_in, const int* in_sizes, int n_in,
                              void* d_out, int out_size) {
    const float* mel_outputs = (const float*)d_in[0];
    const float* mel_targets = (const float*)d_in[1];
    float* out = (float*)d_out;

    stats_kernel<<<K1CTA, 256>>>(mel_targets);
    reduce_stats_kernel<<<(MSZ + PAD + 255) / 256, 256>>>(out);
    rowloss_kernel<<<K3CTA, 256>>>(mel_outputs, mel_targets, out);
}

// round 17
// speedup vs baseline: 1.2155x; 1.0182x over previous
#include <cuda_runtime.h>
#include <math.h>
#include <cstdint>

// Shapes: B=16,T=512,D=80 -> N=8192 rows, K=80
// Algebraic form: rowsum_i = N + o_i.s + 0.5*o_i^T M o_i + (exp(p)-P2(p)),
//   s = sum_j t_j,  M = sum_j t_j t_j^T  (t,o L2-normalized, all fp32)
#define NROWS 8192
#define DDIM  80
#define PAD   81                 // smem row pad (81 coprime 32 -> conflict-free)
#define MSZ   (PAD * PAD)        // 6561
#define K1CTA 512
#define ROWS1 (NROWS / K1CTA)    // 16 t-rows per stats CTA
#define SLABS 4
#define CPS   (K1CTA / SLABS)    // 128 partials per K2 slab
#define K3CTA 256
#define ROWS3 (NROWS / K3CTA)    // 32 rows per rowloss CTA
#define ZCTA  27                 // K1 CTAs that zero g_M/g_s (27*256 >= MSZ+PAD)

// ---------------- scratch (__device__ globals; no allocs allowed) -----------
__device__ float g_Mp[(size_t)K1CTA * MSZ];   // per-CTA M partials (13.4 MB)
__device__ float g_sp[K1CTA * PAD];           // per-CTA s partials
__device__ float g_M[MSZ];
__device__ float g_s[PAD];

// =============== K1: per-CTA M and s partials over 16 t-rows ================
// Also zeroes g_M/g_s/out for this replay (K2 atomicAdds on top; kernel
// boundary orders zero-before-add).
__global__ void __launch_bounds__(256) stats_kernel(const float* __restrict__ t,
                                                    float* __restrict__ out) {
    __shared__ float T[ROWS1][PAD];
    __shared__ float rn[ROWS1];
    int tid = threadIdx.x, b = blockIdx.x;

    if (b < ZCTA) {                          // zero accumulators for replay
        int z = b * 256 + tid;
        if (z < MSZ) g_M[z] = 0.f;
        else if (z < MSZ + PAD) g_s[z - MSZ] = 0.f;
        if (b == 0 && tid == 0) out[0] = 0.f;
    }

    size_t base = (size_t)b * ROWS1 * DDIM;
    for (int i = tid; i < ROWS1 * DDIM; i += 256)
        T[i / DDIM][i % DDIM] = t[base + i];
    __syncthreads();

    if (tid < ROWS1) {                       // row L2 norms
        float s = 0.f;
        #pragma unroll 8
        for (int e = 0; e < DDIM; e++) s = fmaf(T[tid][e], T[tid][e], s);
        rn[tid] = rsqrtf(s);                 // eps branch unreachable (norms ~9)
    }
    __syncthreads();
    for (int i = tid; i < ROWS1 * DDIM; i += 256)
        T[i / DDIM][i % DDIM] *= rn[i / DDIM];
    __syncthreads();

    if (tid < DDIM) {                        // s partial (column sums)
        float s = 0.f;
        #pragma unroll
        for (int r = 0; r < ROWS1; r++) s += T[r][tid];
        g_sp[b * PAD + tid] = s;
    }

    // M partial: each thread owns a 5x5 (d1,d2) block over 16 rows
    int d1 = (tid >> 4) * 5, d2 = (tid & 15) * 5;
    float acc[5][5] = {};
    #pragma unroll 4
    for (int r = 0; r < ROWS1; r++) {
        float a[5], c[5];
        #pragma unroll
        for (int k = 0; k < 5; k++) { a[k] = T[r][d1 + k]; c[k] = T[r][d2 + k]; }
        #pragma unroll
        for (int k = 0; k < 5; k++)
            #pragma unroll
            for (int j = 0; j < 5; j++) acc[k][j] = fmaf(a[k], c[j], acc[k][j]);
    }
    float* mp = g_Mp + (size_t)b * MSZ;
    #pragma unroll
    for (int k = 0; k < 5; k++)
        #pragma unroll
        for (int j = 0; j < 5; j++) mp[(d1 + k) * PAD + (d2 + j)] = acc[k][j];
}

// =============== K2: slab-sum partials -> g_M, g_s (4-way atomics) ==========
__global__ void __launch_bounds__(256) reduce_stats_kernel() {
    int g = blockIdx.x * 256 + threadIdx.x;
    int c0 = blockIdx.y * CPS;
    if (g < MSZ) {
        int e = g / PAD, d = g % PAD;
        if (e < DDIM && d < DDIM) {
            float s0 = 0.f, s1 = 0.f, s2 = 0.f, s3 = 0.f;
            #pragma unroll 4
            for (int c = c0; c < c0 + CPS; c += 4) {
                s0 += g_Mp[(size_t)(c + 0) * MSZ + g];
                s1 += g_Mp[(size_t)(c + 1) * MSZ + g];
                s2 += g_Mp[(size_t)(c + 2) * MSZ + g];
                s3 += g_Mp[(size_t)(c + 3) * MSZ + g];
            }
            atomicAdd(&g_M[g], (s0 + s1) + (s2 + s3));
        }
    } else if (g < MSZ + PAD) {
        int e = g - MSZ;
        if (e < DDIM) {
            float s = 0.f;
            #pragma unroll 4
            for (int c = c0; c < c0 + CPS; c++) s += g_sp[c * PAD + e];
            atomicAdd(&g_s[e], s);
        }
    }
}

// =============== K3: per-row quadratic form + loss ==========================
__global__ void __launch_bounds__(256, 2) rowloss_kernel(
        const float* __restrict__ o, const float* __restrict__ t,
        float* __restrict__ out) {
    __shared__ float Msm[MSZ];               // 26244 B
    __shared__ float Osm[ROWS3][PAD];        // 10368 B
    __shared__ float Tsm[ROWS3][PAD];        // 10368 B
    __shared__ float ssm[PAD];
    __shared__ float rno[ROWS3], pos[ROWS3], qsm[ROWS3];
    __shared__ float wsum[8];

    int tid = threadIdx.x, b = blockIdx.x, lane = tid & 31;
    size_t base = (size_t)b * ROWS3 * DDIM;

    for (int i = tid; i < ROWS3 * DDIM; i += 256) {
        int r = i / DDIM, e = i % DDIM;
        Osm[r][e] = o[base + i];
        Tsm[r][e] = t[base + i];
    }
    for (int i = tid; i < MSZ; i += 256) Msm[i] = g_M[i];
    if (tid < PAD) ssm[tid] = g_s[tid];
    __syncthreads();

    if (tid < ROWS3) {                       // norms + exact fp32 pos
        float so = 0.f, st = 0.f, sd = 0.f;
        #pragma unroll 8
        for (int e = 0; e < DDIM; e++) {
            float a = Osm[tid][e], c = Tsm[tid][e];
            so = fmaf(a, a, so); st = fmaf(c, c, st); sd = fmaf(a, c, sd);
        }
        float rn = rsqrtf(so);
        rno[tid] = rn;
        pos[tid] = sd * rn * rsqrtf(st);
    }
    __syncthreads();
    for (int i = tid; i < ROWS3 * DDIM; i += 256)
        Osm[i / DDIM][i % DDIM] *= rno[i / DDIM];
    __syncthreads();

    // quadratic form q_r = o_r^T M o_r : thread (ty,tx) = 2 rows x 5 dims
    int ty = tid >> 4, tx = tid & 15;
    int r0 = ty * 2, d0 = tx * 5;
    float ob[2][5];
    #pragma unroll
    for (int ri = 0; ri < 2; ri++)
        #pragma unroll
        for (int k = 0; k < 5; k++) ob[ri][k] = Osm[r0 + ri][d0 + k];
    float q0 = 0.f, q1 = 0.f;
    #pragma unroll 8
    for (int e = 0; e < DDIM; e++) {
        const float* mrow = Msm + e * PAD + d0;
        float m0 = mrow[0], m1 = mrow[1], m2 = mrow[2], m3 = mrow[3], m4 = mrow[4];
        float w0 = m0 * ob[0][0];
        w0 = fmaf(m1, ob[0][1], w0); w0 = fmaf(m2, ob[0][2], w0);
        w0 = fmaf(m3, ob[0][3], w0); w0 = fmaf(m4, ob[0][4], w0);
        q0 = fmaf(w0, Osm[r0][e], q0);
        float w1 = m0 * ob[1][0];
        w1 = fmaf(m1, ob[1][1], w1); w1 = fmaf(m2, ob[1][2], w1);
        w1 = fmaf(m3, ob[1][3], w1); w1 = fmaf(m4, ob[1][4], w1);
        q1 = fmaf(w1, Osm[r0 + 1][e], q1);
    }
    #pragma unroll
    for (int m = 8; m > 0; m >>= 1) {        // reduce over 16 tx lanes
        q0 += __shfl_xor_sync(0xffffffffu, q0, m);
        q1 += __shfl_xor_sync(0xffffffffu, q1, m);
    }
    if (tx == 0) { qsm[r0] = q0; qsm[r0 + 1] = q1; }
    __syncthreads();

    // finalize rows + CTA reduction
    float loss = 0.f;
    if (tid < ROWS3) {
        float lin = 0.f;
        #pragma unroll 8
        for (int e = 0; e < DDIM; e++) lin = fmaf(ssm[e], Osm[tid][e], lin);
        float p = pos[tid];
        float corr = __expf(p) - fmaf(fmaf(p, 0.5f, 1.0f), p, 1.0f);
        float rowsum = (float)NROWS + lin + 0.5f * qsm[tid] + corr;
        loss = __logf(rowsum) - p;
    }
    #pragma unroll
    for (int m = 16; m > 0; m >>= 1) loss += __shfl_xor_sync(0xffffffffu, loss, m);
    if (lane == 0) wsum[tid >> 5] = loss;
    __syncthreads();
    if (tid == 0) {
        float v = wsum[0] + wsum[1];         // warp 0 carries rows; wsum[1]=0
        atomicAdd(out, v * (1.0f / (float)NROWS));
    }
}

extern "C" void kernel_launch(void* const* d_in, const int* in_sizes, int n_in,
                              void* d_out, int out_size) {
    const float* mel_outputs = (const float*)d_in[0];
    const float* mel_targets = (const float*)d_in[1];
    float* out = (float*)d_out;

    stats_kernel<<<K1CTA, 256>>>(mel_targets, out);
    reduce_stats_kernel<<<dim3(ZCTA, SLABS), 256>>>();
    rowloss_kernel<<<K3CTA, 256>>>(mel_outputs, mel_targets, out);
}